// round 15
// baseline (speedup 1.0000x reference)
#include <cuda_runtime.h>
#include <cuda_fp16.h>
#include <cstdint>

// Problem constants
#define BB 8
#define LL 1024
#define DD 768
#define HH 12
#define DHH 64
#define MM (BB*LL)   // 8192
#define LOG2E 1.4426950408889634f

// ---------------------------------------------------------------------------
// Scratch (device globals — no allocation allowed)
// ---------------------------------------------------------------------------
__device__ __half g_q16[BB*HH*LL*DHH];     // [B,H,L,Dh], pre-scaled by log2e/8
__device__ __half g_k16[BB*HH*LL*DHH];
__device__ __half g_v16[BB*HH*LL*DHH];
__device__ __half g_c16[MM*DD];            // attention context [M, D]
__device__ __half g_w16[4][DD*DD];         // fp16 weights
__device__ uint32_t g_mbits[BB*LL*(LL/32)];
__device__ unsigned char g_mflags[BB*8*8];
// Consolidated counters (memset to 0 each launch):
//   [0,64)    attn->out, per (b, qtile128), target 12
//   [64,208)  qkv->attn, per (b*6+nt)*3+z, target 8
//   [208,232) weights,   per z*6+nt,       target 4
//   [232]     mask done,                   target 512
__device__ int g_ctr[256];

// ---------------------------------------------------------------------------
// PTX helpers — baseline (non-'a') features only
// ---------------------------------------------------------------------------
__device__ __forceinline__ uint32_t smem_u32(const void* p) {
    uint32_t a;
    asm("{ .reg .u64 t; cvta.to.shared.u64 t, %1; cvt.u32.u64 %0, t; }"
        : "=r"(a) : "l"(p));
    return a;
}
__device__ __forceinline__ void cp_async16(uint32_t saddr, const void* gptr) {
    asm volatile("cp.async.cg.shared.global [%0], [%1], 16;"
                 :: "r"(saddr), "l"(gptr) : "memory");
}
__device__ __forceinline__ void cp_commit() {
    asm volatile("cp.async.commit_group;" ::: "memory");
}
template<int N>
__device__ __forceinline__ void cp_wait() {
    asm volatile("cp.async.wait_group %0;" :: "n"(N) : "memory");
}
__device__ __forceinline__ void ldmatrix_x4(uint32_t& r0, uint32_t& r1,
                                            uint32_t& r2, uint32_t& r3,
                                            uint32_t addr) {
    asm volatile("ldmatrix.sync.aligned.m8n8.x4.shared.b16 {%0,%1,%2,%3}, [%4];"
                 : "=r"(r0), "=r"(r1), "=r"(r2), "=r"(r3) : "r"(addr));
}
__device__ __forceinline__ void ldmatrix_x4_t(uint32_t& r0, uint32_t& r1,
                                              uint32_t& r2, uint32_t& r3,
                                              uint32_t addr) {
    asm volatile("ldmatrix.sync.aligned.m8n8.x4.trans.shared.b16 {%0,%1,%2,%3}, [%4];"
                 : "=r"(r0), "=r"(r1), "=r"(r2), "=r"(r3) : "r"(addr));
}
__device__ __forceinline__ void mma_f16(float* c, const uint32_t* a,
                                        uint32_t b0, uint32_t b1) {
    asm volatile(
        "mma.sync.aligned.m16n8k16.row.col.f32.f16.f16.f32 "
        "{%0,%1,%2,%3}, {%4,%5,%6,%7}, {%8,%9}, {%0,%1,%2,%3};"
        : "+f"(c[0]), "+f"(c[1]), "+f"(c[2]), "+f"(c[3])
        : "r"(a[0]), "r"(a[1]), "r"(a[2]), "r"(a[3]), "r"(b0), "r"(b1));
}
__device__ __forceinline__ uint32_t pack_h2(float a, float b) {
    __half2 h = __floats2half2_rn(a, b);
    return *reinterpret_cast<uint32_t*>(&h);
}
__device__ __forceinline__ uint32_t ex2_h2(uint32_t x) {
    uint32_t r;
    asm("ex2.approx.f16x2 %0, %1;" : "=r"(r) : "r"(x));
    return r;
}

// ---------------------------------------------------------------------------
// Mega kernel, 3296 blocks:
//   [0,96)      weight fp32->fp16 converts       (bump g_ctr[208+z*6+nt])
//   [96,608)    mask pack + flags                (bump g_ctr[232])
//   [608,1760)  qkv projections                  (wait weights; bump qkv ctr)
//   [1760,2528) attention                        (wait qkv + mask; bump g_sync)
//   [2528,3296) out projection                   (wait g_sync + z3 weights)
// All waits point to strictly lower block IDs -> queue order, no deadlock.
// ---------------------------------------------------------------------------
#define PH      80                       // GEMM smem pitch (64B data + 16 pad)
#define TILE_B  (128 * PH)               // 10240
#define STAGE_B (2 * TILE_B)             // 20480
#define NCHUNK  (DD / 32)                // 24

#define AROWB   144                     // attention pitch (128B data + 16 pad)
#define QTILE_B (128 * AROWB)           // 18432
#define KTILE_B (64 * AROWB)            // 9216
#define ASMEM   (QTILE_B + 4 * KTILE_B) // 55296
#define OA_TILE (64 * PH)               // 5120
#define OSTAGE  (OA_TILE + 128 * PH)    // 15360

__global__ __launch_bounds__(256, 2)
void mha_mega(const float* __restrict__ Q, const float* __restrict__ K,
              const float* __restrict__ V, const unsigned char* __restrict__ mask,
              const float* __restrict__ w0, const float* __restrict__ w1,
              const float* __restrict__ w2, const float* __restrict__ w3,
              const float* __restrict__ bq, const float* __restrict__ bk,
              const float* __restrict__ bv,
              const float* __restrict__ bias_o, float* __restrict__ out)
{
    extern __shared__ __align__(128) char smem[];
    const uint32_t sb = smem_u32(smem);
    const int tid = threadIdx.x, wid = tid >> 5, lane = tid & 31;

    if (blockIdx.x < 96) {
        // =================== WEIGHT CONVERT ROLE ===================
        const int wbid = blockIdx.x;
        int z, nt, q;
        if (wbid < 72) { nt = wbid / 12; int r = wbid % 12; z = r >> 2; q = r & 3; }
        else           { z = 3; nt = (wbid - 72) >> 2; q = wbid & 3; }
        const float* src = (z == 0) ? w0 : (z == 1) ? w1 : (z == 2) ? w2 : w3;
        uint32_t* dp = reinterpret_cast<uint32_t*>(g_w16[z]);
        const int base4 = ((nt * 128 + q * 32) * DD) >> 2;   // float4 index
        #pragma unroll
        for (int it = 0; it < 24; it++) {
            int i = base4 + it * 256 + tid;
            float4 f = reinterpret_cast<const float4*>(src)[i];
            dp[2*i]   = pack_h2(f.x, f.y);
            dp[2*i+1] = pack_h2(f.z, f.w);
        }
        __syncthreads();
        if (tid == 0) {
            __threadfence();
            atomicAdd(&g_ctr[208 + z * 6 + nt], 1);
        }

    } else if (blockIdx.x < 608) {
        // =================== MASK PACK ROLE ===================
        const int mbid = blockIdx.x - 96;
        const int kt = mbid & 7, qt = (mbid >> 3) & 7, b = mbid >> 6;
        uint32_t any = 0;
        #pragma unroll
        for (int k = 0; k < 2; k++) {
            int widx = tid * 2 + k;              // 0..511
            int row  = widx >> 2;                // 0..127
            int wc   = widx & 3;
            const uint4* p = reinterpret_cast<const uint4*>(
                mask + ((size_t)(b * LL + qt * 128 + row)) * LL + kt * 128 + wc * 32);
            uint4 u0 = p[0], u1 = p[1];
            uint32_t ws[8] = {u0.x, u0.y, u0.z, u0.w, u1.x, u1.y, u1.z, u1.w};
            uint32_t r = 0;
            #pragma unroll
            for (int w = 0; w < 8; w++)
                #pragma unroll
                for (int kk = 0; kk < 4; kk++)
                    if ((ws[w] >> (8 * kk)) & 0xFFu) r |= 1u << (w * 4 + kk);
            g_mbits[((size_t)(b * LL + qt * 128 + row)) * (LL / 32) + kt * 4 + wc] = r;
            any |= r;
        }
        int f = __syncthreads_or(any != 0);
        if (tid == 0) {
            g_mflags[(b * 8 + qt) * 8 + kt] = (unsigned char)f;
            __threadfence();
            atomicAdd(&g_ctr[232], 1);
        }

    } else if (blockIdx.x < 1760) {
        // =================== QKV PROJECTION ROLE ===================
        const int id = blockIdx.x - 608;
        const int z    = id % 3;
        const int t3   = id / 3;
        const int mloc = t3 & 7;
        const int t8   = t3 >> 3;
        const int nt   = t8 % 6;
        const int b    = t8 / 6;
        const int m0 = (b * 8 + mloc) * 128, n0 = nt * 128;
        const int wm = wid & 3, wn = wid >> 2;

        if (tid == 0) {
            while (atomicAdd(&g_ctr[208 + z * 6 + nt], 0) < 4) __nanosleep(64);
            __threadfence();
        }
        __syncthreads();

        const float* A = ((z == 0) ? Q : (z == 1) ? K : V) + (size_t)m0 * DD;
        const __half* B = g_w16[z] + (size_t)n0 * DD;
        const float* bias = (z == 0) ? bq : (z == 1) ? bk : bv;
        __half* oh = (z == 0) ? g_q16 : (z == 1) ? g_k16 : g_v16;
        const float scale = (z == 0) ? 0.125f * LOG2E : 1.0f;

        const int arow[4] = { tid >> 3, (tid + 256) >> 3,
                              (tid + 512) >> 3, (tid + 768) >> 3 };
        const int afsg = tid & 7;

        float4 abuf[4];
        auto ldg_A = [&](int kc) {
            const float* g = A + kc * 32 + afsg * 4;
            #pragma unroll
            for (int t = 0; t < 4; t++)
                abuf[t] = *reinterpret_cast<const float4*>(g + (size_t)arow[t] * DD);
        };
        auto sts_A = [&](int st) {
            char* base = smem + st * STAGE_B;
            #pragma unroll
            for (int t = 0; t < 4; t++) {
                uint2 h;
                h.x = pack_h2(abuf[t].x, abuf[t].y);
                h.y = pack_h2(abuf[t].z, abuf[t].w);
                *reinterpret_cast<uint2*>(base + arow[t] * PH + afsg * 8) = h;
            }
        };
        auto cp_B = [&](int kc, int st) {
            #pragma unroll
            for (int t = 0; t < 2; t++) {
                int iid = tid + t * 256;
                int row = iid >> 2, seg = iid & 3;
                cp_async16(sb + st * STAGE_B + TILE_B + row * PH + seg * 16,
                           B + (size_t)row * DD + kc * 32 + seg * 8);
            }
            cp_commit();
        };

        float acc[2][8][4];
        #pragma unroll
        for (int i = 0; i < 2; i++)
            #pragma unroll
            for (int j = 0; j < 8; j++)
                #pragma unroll
                for (int k = 0; k < 4; k++) acc[i][j][k] = 0.f;

        ldg_A(0);
        cp_B(0, 0);

        const int lrow = lane & 15;
        const int lhalf = lane >> 4;

        #pragma unroll 1
        for (int c = 0; c < NCHUNK; c++) {
            const int s = c & 1;
            sts_A(s);
            if (c + 1 < NCHUNK) {
                ldg_A(c + 1);
                cp_B(c + 1, s ^ 1);
                cp_wait<1>();
            } else {
                cp_wait<0>();
            }
            __syncthreads();

            const uint32_t stg = sb + s * STAGE_B;
            #pragma unroll
            for (int ks = 0; ks < 2; ks++) {
                const int seg = ks * 2 + lhalf;
                uint32_t ah[2][4];
                #pragma unroll
                for (int mf = 0; mf < 2; mf++) {
                    uint32_t off = (uint32_t)((wm * 32 + mf * 16 + lrow) * PH + seg * 16);
                    ldmatrix_x4(ah[mf][0], ah[mf][1], ah[mf][2], ah[mf][3], stg + off);
                }
                #pragma unroll
                for (int ng = 0; ng < 4; ng++) {
                    uint32_t off = (uint32_t)((wn * 64 + ng * 16 + lrow) * PH + seg * 16);
                    uint32_t b0, b1, b2, b3;
                    ldmatrix_x4(b0, b1, b2, b3, stg + TILE_B + off);
                    #pragma unroll
                    for (int mf = 0; mf < 2; mf++) {
                        mma_f16(acc[mf][2*ng  ], ah[mf], b0, b2);
                        mma_f16(acc[mf][2*ng+1], ah[mf], b1, b3);
                    }
                }
            }
            __syncthreads();
        }

        #pragma unroll
        for (int nf = 0; nf < 8; nf++) {
            const int col = n0 + wn * 64 + nf * 8 + (lane & 3) * 2;
            const float b0 = bias[col], b1 = bias[col + 1];
            #pragma unroll
            for (int mf = 0; mf < 2; mf++) {
                const int r0 = m0 + wm * 32 + mf * 16 + (lane >> 2);
                const float* a = acc[mf][nf];
                #pragma unroll
                for (int half = 0; half < 2; half++) {
                    const int m = r0 + half * 8;
                    uint32_t hp = pack_h2((a[2*half] + b0) * scale,
                                          (a[2*half+1] + b1) * scale);
                    int bb = m >> 10, l = m & 1023;
                    int hh = col >> 6, d = col & 63;
                    size_t idx = (((size_t)(bb * HH + hh) << 10) + l) * DHH + d;
                    *reinterpret_cast<uint32_t*>(oh + idx) = hp;
                }
            }
        }

        __syncthreads();
        if (tid == 0) {
            __threadfence();
            atomicAdd(&g_ctr[64 + (b * 6 + nt) * 3 + z], 1);
        }

    } else if (blockIdx.x < 2528) {
        // =================== ATTENTION ROLE ===================
        const int id = blockIdx.x - 1760;
        const int qt = id & 7, h = (id >> 3) % 12, b = id / 96;
        const int q0 = qt * 128;
        const size_t hb = ((size_t)(b * HH + h)) << 16;

        if (tid == 0) {
            const int base = 64 + (b * 6 + (h >> 1)) * 3;
            while (atomicAdd(&g_ctr[base + 0], 0) < 8 ||
                   atomicAdd(&g_ctr[base + 1], 0) < 8 ||
                   atomicAdd(&g_ctr[base + 2], 0) < 8 ||
                   atomicAdd(&g_ctr[232], 0) < 512) __nanosleep(128);
            __threadfence();
        }
        __syncthreads();

        const uint32_t SQ = sb;
        auto stage = [&](int s) { return sb + QTILE_B + (uint32_t)s * 2 * KTILE_B; };

        auto load_q = [&]() {
            const __half* g = g_q16 + hb + (size_t)q0 * 64;
            #pragma unroll
            for (int it = 0; it < 4; it++) {
                int iid = tid + it * 256;
                int row = iid >> 3, seg = iid & 7;
                cp_async16(SQ + row * AROWB + seg * 16, g + (size_t)row * 64 + seg * 8);
            }
            cp_commit();
        };
        auto load_kv = [&](int t, int s) {
            const size_t off = hb + (size_t)t * 64 * 64;
            uint32_t st = stage(s);
            #pragma unroll
            for (int it = 0; it < 2; it++) {
                int iid = tid + it * 256;
                int row = iid >> 3, seg = iid & 7;
                cp_async16(st + row * AROWB + seg * 16,
                           g_k16 + off + (size_t)row * 64 + seg * 8);
                cp_async16(st + KTILE_B + row * AROWB + seg * 16,
                           g_v16 + off + (size_t)row * 64 + seg * 8);
            }
            cp_commit();
        };

        load_q();
        load_kv(0, 0);
        cp_wait<1>();
        __syncthreads();

        const int lr = lane & 15, lh = lane >> 4;
        uint32_t qf[4][4];
        #pragma unroll
        for (int ks = 0; ks < 4; ks++) {
            uint32_t off = (uint32_t)((wid * 16 + lr) * AROWB + ks * 32 + lh * 16);
            ldmatrix_x4(qf[ks][0], qf[ks][1], qf[ks][2], qf[ks][3], SQ + off);
        }

        float mA = -INFINITY, mB = -INFINITY, lA = 0.f, lB = 0.f;
        float o[8][4];
        #pragma unroll
        for (int i = 0; i < 8; i++)
            #pragma unroll
            for (int j = 0; j < 4; j++) o[i][j] = 0.f;

        const unsigned char* flagp = g_mflags + (b * 8 + qt) * 8;
        const uint32_t ONES2 = 0x3C003C00u;   // half2(1.0, 1.0)

        #pragma unroll 1
        for (int t = 0; t < 16; t++) {
            if (t < 15) { load_kv(t + 1, (t + 1) & 1); cp_wait<1>(); }
            else        { cp_wait<0>(); }
            __syncthreads();
            const uint32_t st = stage(t & 1);

            float s[8][4];
            #pragma unroll
            for (int j = 0; j < 8; j++)
                #pragma unroll
                for (int k = 0; k < 4; k++) s[j][k] = 0.f;

            #pragma unroll
            for (int ks = 0; ks < 4; ks++) {
                #pragma unroll
                for (int ng = 0; ng < 4; ng++) {
                    uint32_t off = (uint32_t)((ng * 16 + lr) * AROWB + ks * 32 + lh * 16);
                    uint32_t k0, k1, k2, k3;
                    ldmatrix_x4(k0, k1, k2, k3, st + off);
                    mma_f16(s[2*ng  ], qf[ks], k0, k2);
                    mma_f16(s[2*ng+1], qf[ks], k1, k3);
                }
            }

            if (flagp[t >> 1]) {
                const uint32_t* mr = g_mbits
                    + ((size_t)(b * LL + q0 + wid * 16 + (lane >> 2))) * (LL / 32) + t * 2;
                uint32_t wA[2], wB[2];
                #pragma unroll
                for (int ww = 0; ww < 2; ww++) { wA[ww] = mr[ww]; wB[ww] = mr[8 * (LL/32) + ww]; }
                #pragma unroll
                for (int j = 0; j < 8; j++) {
                    int bp = (j & 3) * 8 + (lane & 3) * 2;
                    uint32_t a = wA[j >> 2], bw = wB[j >> 2];
                    if ((a  >> bp)      & 1u) s[j][0] = -INFINITY;
                    if ((a  >> (bp+1))  & 1u) s[j][1] = -INFINITY;
                    if ((bw >> bp)      & 1u) s[j][2] = -INFINITY;
                    if ((bw >> (bp+1))  & 1u) s[j][3] = -INFINITY;
                }
            }

            float mxA = -INFINITY, mxB = -INFINITY;
            #pragma unroll
            for (int j = 0; j < 8; j++) {
                mxA = fmaxf(mxA, fmaxf(s[j][0], s[j][1]));
                mxB = fmaxf(mxB, fmaxf(s[j][2], s[j][3]));
            }
            mxA = fmaxf(mxA, __shfl_xor_sync(0xffffffffu, mxA, 1));
            mxA = fmaxf(mxA, __shfl_xor_sync(0xffffffffu, mxA, 2));
            mxB = fmaxf(mxB, __shfl_xor_sync(0xffffffffu, mxB, 1));
            mxB = fmaxf(mxB, __shfl_xor_sync(0xffffffffu, mxB, 2));
            float mnA = fmaxf(mA, mxA), mnB = fmaxf(mB, mxB);
            float aA = (mA == -INFINITY) ? 0.f : exp2f(mA - mnA);
            float aB = (mB == -INFINITY) ? 0.f : exp2f(mB - mnB);
            float subA = (mnA == -INFINITY) ? 0.f : mnA;
            float subB = (mnB == -INFINITY) ? 0.f : mnB;
            mA = mnA; mB = mnB;
            if (aA != 1.f || aB != 1.f) {
                #pragma unroll
                for (int nf = 0; nf < 8; nf++) {
                    o[nf][0] *= aA; o[nf][1] *= aA;
                    o[nf][2] *= aB; o[nf][3] *= aB;
                }
            }

            float sf[4] = {0.f, 0.f, 0.f, 0.f};
            #pragma unroll
            for (int ks = 0; ks < 4; ks++) {
                uint32_t ap[4];
                ap[0] = ex2_h2(pack_h2(s[2*ks  ][0] - subA, s[2*ks  ][1] - subA));
                ap[1] = ex2_h2(pack_h2(s[2*ks  ][2] - subB, s[2*ks  ][3] - subB));
                ap[2] = ex2_h2(pack_h2(s[2*ks+1][0] - subA, s[2*ks+1][1] - subA));
                ap[3] = ex2_h2(pack_h2(s[2*ks+1][2] - subB, s[2*ks+1][3] - subB));
                mma_f16(sf, ap, ONES2, ONES2);   // col = row sum of P
                #pragma unroll
                for (int ng = 0; ng < 4; ng++) {
                    uint32_t voff = (uint32_t)((ks * 16 + lr) * AROWB + ng * 32 + lh * 16);
                    uint32_t v0, v1, v2, v3;
                    ldmatrix_x4_t(v0, v1, v2, v3, st + KTILE_B + voff);
                    mma_f16(o[2*ng  ], ap, v0, v1);
                    mma_f16(o[2*ng+1], ap, v2, v3);
                }
            }
            lA = lA * aA + sf[0];
            lB = lB * aB + sf[2];
            __syncthreads();
        }

        float iA = (lA > 0.f) ? (1.f / lA) : 0.f;
        float iB = (lB > 0.f) ? (1.f / lB) : 0.f;
        size_t rowA = (size_t)b * LL + q0 + wid * 16 + (lane >> 2);
        size_t rowB = rowA + 8;
        #pragma unroll
        for (int nf = 0; nf < 8; nf++) {
            int col = h * 64 + nf * 8 + (lane & 3) * 2;
            *reinterpret_cast<uint32_t*>(g_c16 + rowA * DD + col)
                = pack_h2(o[nf][0] * iA, o[nf][1] * iA);
            *reinterpret_cast<uint32_t*>(g_c16 + rowB * DD + col)
                = pack_h2(o[nf][2] * iB, o[nf][3] * iB);
        }

        __syncthreads();
        if (tid == 0) {
            __threadfence();
            atomicAdd(&g_ctr[b * 8 + qt], 1);
        }
    } else {
        // =================== OUT-PROJECTION ROLE ===================
        const int oid = blockIdx.x - 2528;     // 768 tiles: 128 m x 6 n
        const int mt = oid & 127;
        const int nt = oid >> 7;
        const int wm = wid & 3, wn = wid >> 2;

        const int flag = (mt >> 4) * 8 + ((mt & 15) >> 1);
        if (tid == 0) {
            while (atomicAdd(&g_ctr[flag], 0) < HH ||
                   atomicAdd(&g_ctr[208 + 18 + nt], 0) < 4) __nanosleep(128);
            __threadfence();
        }
        __syncthreads();

        const __half* A = g_c16 + (size_t)mt * 64 * DD;
        const __half* B = g_w16[3] + (size_t)nt * 128 * DD;

        auto load_chunk = [&](int kc, int st) {
            #pragma unroll
            for (int t = 0; t < 3; t++) {
                int iid = tid + t * 256;            // 0..767
                uint32_t dst; const __half* src;
                if (iid < 256) {
                    int row = iid >> 2, seg = iid & 3;
                    dst = sb + st * OSTAGE + row * PH + seg * 16;
                    src = A + (size_t)row * DD + kc * 32 + seg * 8;
                } else {
                    int rem = iid - 256;
                    int row = rem >> 2, seg = rem & 3;
                    dst = sb + st * OSTAGE + OA_TILE + row * PH + seg * 16;
                    src = B + (size_t)row * DD + kc * 32 + seg * 8;
                }
                cp_async16(dst, src);
            }
            cp_commit();
        };

        float acc[8][4];
        #pragma unroll
        for (int j = 0; j < 8; j++)
            #pragma unroll
            for (int k = 0; k < 4; k++) acc[j][k] = 0.f;

        load_chunk(0, 0);

        const int lrow = lane & 15;
        const int lhalf = lane >> 4;

        #pragma unroll 1
        for (int c = 0; c < NCHUNK; c++) {
            const int s = c & 1;
            if (c + 1 < NCHUNK) { load_chunk(c + 1, s ^ 1); cp_wait<1>(); }
            else                { cp_wait<0>(); }
            __syncthreads();

            const uint32_t stg = sb + s * OSTAGE;
            #pragma unroll
            for (int ks = 0; ks < 2; ks++) {
                const int seg = ks * 2 + lhalf;
                uint32_t ah[4];
                uint32_t aoff = (uint32_t)((wm * 16 + lrow) * PH + seg * 16);
                ldmatrix_x4(ah[0], ah[1], ah[2], ah[3], stg + aoff);
                #pragma unroll
                for (int ng = 0; ng < 4; ng++) {
                    uint32_t boff = (uint32_t)((wn * 64 + ng * 16 + lrow) * PH + seg * 16);
                    uint32_t b0, b1, b2, b3;
                    ldmatrix_x4(b0, b1, b2, b3, stg + OA_TILE + boff);
                    mma_f16(acc[2*ng  ], ah, b0, b2);
                    mma_f16(acc[2*ng+1], ah, b1, b3);
                }
            }
            __syncthreads();
        }

        #pragma unroll
        for (int nf = 0; nf < 8; nf++) {
            const int col = nt * 128 + wn * 64 + nf * 8 + (lane & 3) * 2;
            const float b0 = bias_o[col], b1 = bias_o[col + 1];
            const int r0 = mt * 64 + wm * 16 + (lane >> 2);
            #pragma unroll
            for (int half = 0; half < 2; half++) {
                const int m = r0 + half * 8;
                *reinterpret_cast<float2*>(out + (size_t)m * DD + col)
                    = make_float2(acc[nf][2*half] + b0, acc[nf][2*half+1] + b1);
            }
        }
    }
}

// ---------------------------------------------------------------------------
extern "C" void kernel_launch(void* const* d_in, const int* in_sizes, int n_in,
                              void* d_out, int out_size)
{
    const float* Query = (const float*)d_in[0];
    const float* Key   = (const float*)d_in[1];
    const float* Value = (const float*)d_in[2];
    const unsigned char* maskp = (const unsigned char*)d_in[3];
    const float* WQ_b = (const float*)d_in[5];
    const float* WK_b = (const float*)d_in[7];
    const float* WV_b = (const float*)d_in[9];
    const float* WO_b = (const float*)d_in[11];
    float* out = (float*)d_out;

    cudaFuncSetAttribute(mha_mega, cudaFuncAttributeMaxDynamicSharedMemorySize,
                         ASMEM);

    // Reset dataflow counters (graph-capturable, no allocation)
    void* ctrp;
    cudaGetSymbolAddress(&ctrp, g_ctr);
    cudaMemsetAsync(ctrp, 0, 256 * sizeof(int));

    // Entire pipeline: one launch
    mha_mega<<<3296, 256, ASMEM>>>(Query, Key, Value, maskp,
                                   (const float*)d_in[4], (const float*)d_in[6],
                                   (const float*)d_in[8], (const float*)d_in[10],
                                   WQ_b, WK_b, WV_b, WO_b, out);
}

// round 16
// speedup vs baseline: 1.0235x; 1.0235x over previous
#include <cuda_runtime.h>
#include <cuda_fp16.h>
#include <cstdint>

// Problem constants
#define BB 8
#define LL 1024
#define DD 768
#define HH 12
#define DHH 64
#define MM (BB*LL)   // 8192
#define LOG2E 1.4426950408889634f

// ---------------------------------------------------------------------------
// Scratch (device globals — no allocation allowed)
// ---------------------------------------------------------------------------
__device__ __half g_q16[BB*HH*LL*DHH];     // [B,H,L,Dh], pre-scaled by log2e/8
__device__ __half g_k16[BB*HH*LL*DHH];
__device__ __half g_v16[BB*HH*LL*DHH];
__device__ __half g_c16[MM*DD];            // attention context [M, D]
__device__ __half g_w16[4][DD*DD];         // fp16 weights
__device__ uint32_t g_mbits[BB*LL*(LL/32)];
__device__ unsigned char g_mflags[BB*8*8];
__device__ int g_sync[BB*8];               // attn->out: per (b, qtile128), target 12
__device__ int g_qkv[BB*6*3];              // qkv->attn: per (b, ntile, z), target 8

// ---------------------------------------------------------------------------
// PTX helpers — baseline (non-'a') features only
// ---------------------------------------------------------------------------
__device__ __forceinline__ uint32_t smem_u32(const void* p) {
    uint32_t a;
    asm("{ .reg .u64 t; cvta.to.shared.u64 t, %1; cvt.u32.u64 %0, t; }"
        : "=r"(a) : "l"(p));
    return a;
}
__device__ __forceinline__ void cp_async16(uint32_t saddr, const void* gptr) {
    asm volatile("cp.async.cg.shared.global [%0], [%1], 16;"
                 :: "r"(saddr), "l"(gptr) : "memory");
}
__device__ __forceinline__ void cp_commit() {
    asm volatile("cp.async.commit_group;" ::: "memory");
}
template<int N>
__device__ __forceinline__ void cp_wait() {
    asm volatile("cp.async.wait_group %0;" :: "n"(N) : "memory");
}
__device__ __forceinline__ void ldmatrix_x4(uint32_t& r0, uint32_t& r1,
                                            uint32_t& r2, uint32_t& r3,
                                            uint32_t addr) {
    asm volatile("ldmatrix.sync.aligned.m8n8.x4.shared.b16 {%0,%1,%2,%3}, [%4];"
                 : "=r"(r0), "=r"(r1), "=r"(r2), "=r"(r3) : "r"(addr));
}
__device__ __forceinline__ void ldmatrix_x4_t(uint32_t& r0, uint32_t& r1,
                                              uint32_t& r2, uint32_t& r3,
                                              uint32_t addr) {
    asm volatile("ldmatrix.sync.aligned.m8n8.x4.trans.shared.b16 {%0,%1,%2,%3}, [%4];"
                 : "=r"(r0), "=r"(r1), "=r"(r2), "=r"(r3) : "r"(addr));
}
__device__ __forceinline__ void mma_f16(float* c, const uint32_t* a,
                                        uint32_t b0, uint32_t b1) {
    asm volatile(
        "mma.sync.aligned.m16n8k16.row.col.f32.f16.f16.f32 "
        "{%0,%1,%2,%3}, {%4,%5,%6,%7}, {%8,%9}, {%0,%1,%2,%3};"
        : "+f"(c[0]), "+f"(c[1]), "+f"(c[2]), "+f"(c[3])
        : "r"(a[0]), "r"(a[1]), "r"(a[2]), "r"(a[3]), "r"(b0), "r"(b1));
}
__device__ __forceinline__ uint32_t pack_h2(float a, float b) {
    __half2 h = __floats2half2_rn(a, b);
    return *reinterpret_cast<uint32_t*>(&h);
}
__device__ __forceinline__ uint32_t ex2_h2(uint32_t x) {
    uint32_t r;
    asm("ex2.approx.f16x2 %0, %1;" : "=r"(r) : "r"(x));
    return r;
}

// ---------------------------------------------------------------------------
// Prep kernel: blocks [0,512) pack mask bits + per-tile flags + reset counters;
// blocks [512,1088) convert weights fp32->fp16 (4 float4 per thread).
// ---------------------------------------------------------------------------
__global__ __launch_bounds__(256)
void prep_all(const unsigned char* __restrict__ mask,
              const float* __restrict__ w0, const float* __restrict__ w1,
              const float* __restrict__ w2, const float* __restrict__ w3)
{
    if (blockIdx.x < 512) {
        const int kt = blockIdx.x & 7, qt = (blockIdx.x >> 3) & 7, b = blockIdx.x >> 6;
        if (kt == 0 && threadIdx.x == 0) g_sync[b * 8 + qt] = 0;
        if (blockIdx.x == 0 && threadIdx.x < BB * 6 * 3) g_qkv[threadIdx.x] = 0;
        uint32_t any = 0;
        #pragma unroll
        for (int k = 0; k < 2; k++) {
            int widx = threadIdx.x * 2 + k;      // 0..511
            int row  = widx >> 2;                // 0..127
            int wc   = widx & 3;
            const uint4* p = reinterpret_cast<const uint4*>(
                mask + ((size_t)(b * LL + qt * 128 + row)) * LL + kt * 128 + wc * 32);
            uint4 u0 = p[0], u1 = p[1];
            uint32_t ws[8] = {u0.x, u0.y, u0.z, u0.w, u1.x, u1.y, u1.z, u1.w};
            uint32_t r = 0;
            #pragma unroll
            for (int w = 0; w < 8; w++)
                #pragma unroll
                for (int kk = 0; kk < 4; kk++)
                    if ((ws[w] >> (8 * kk)) & 0xFFu) r |= 1u << (w * 4 + kk);
            g_mbits[((size_t)(b * LL + qt * 128 + row)) * (LL / 32) + kt * 4 + wc] = r;
            any |= r;
        }
        int f = __syncthreads_or(any != 0);
        if (threadIdx.x == 0) g_mflags[(b * 8 + qt) * 8 + kt] = (unsigned char)f;
    } else {
        const int id = blockIdx.x - 512;         // 0..575
        const int z = id / 144;                  // 144 blocks per weight
        const float* src = (z == 0) ? w0 : (z == 1) ? w1 : (z == 2) ? w2 : w3;
        uint32_t* dp = reinterpret_cast<uint32_t*>(g_w16[z]);
        const int base = (id % 144) * 1024 + threadIdx.x;
        #pragma unroll
        for (int t = 0; t < 4; t++) {
            int i = base + t * 256;
            float4 f = reinterpret_cast<const float4*>(src)[i];
            dp[2*i]   = pack_h2(f.x, f.y);
            dp[2*i+1] = pack_h2(f.z, f.w);
        }
    }
}

// ---------------------------------------------------------------------------
// Mega kernel: qkv-proj [0,1152) -> attention [1152,1920) -> out-proj [1920,2688)
// (R14 structure: double-buffered; f16x2 ex2 softmax + ones-MMA row sums)
// ---------------------------------------------------------------------------
#define PH      80                       // GEMM smem pitch (64B data + 16 pad)
#define TILE_B  (128 * PH)               // 10240
#define STAGE_B (2 * TILE_B)             // 20480
#define NCHUNK  (DD / 32)                // 24

#define AROWB   144                     // attention pitch (128B data + 16 pad)
#define QTILE_B (128 * AROWB)           // 18432
#define KTILE_B (64 * AROWB)            // 9216
#define ASMEM   (QTILE_B + 4 * KTILE_B) // 55296
#define OA_TILE (64 * PH)               // 5120
#define OSTAGE  (OA_TILE + 128 * PH)    // 15360

__global__ __launch_bounds__(256, 2)
void mha_mega(const float* __restrict__ Q, const float* __restrict__ K,
              const float* __restrict__ V,
              const float* __restrict__ bq, const float* __restrict__ bk,
              const float* __restrict__ bv,
              const float* __restrict__ bias_o, float* __restrict__ out)
{
    extern __shared__ __align__(128) char smem[];
    const uint32_t sb = smem_u32(smem);
    const int tid = threadIdx.x, wid = tid >> 5, lane = tid & 31;

    if (blockIdx.x < 1152) {
        // =================== QKV PROJECTION ROLE ===================
        const int id = blockIdx.x;
        const int z    = id % 3;
        const int t3   = id / 3;
        const int mloc = t3 & 7;
        const int t8   = t3 >> 3;
        const int nt   = t8 % 6;
        const int b    = t8 / 6;
        const int m0 = (b * 8 + mloc) * 128, n0 = nt * 128;
        const int wm = wid & 3, wn = wid >> 2;

        const float* A = ((z == 0) ? Q : (z == 1) ? K : V) + (size_t)m0 * DD;
        const __half* B = g_w16[z] + (size_t)n0 * DD;
        const float* bias = (z == 0) ? bq : (z == 1) ? bk : bv;
        __half* oh = (z == 0) ? g_q16 : (z == 1) ? g_k16 : g_v16;
        const float scale = (z == 0) ? 0.125f * LOG2E : 1.0f;

        const int arow[4] = { tid >> 3, (tid + 256) >> 3,
                              (tid + 512) >> 3, (tid + 768) >> 3 };
        const int afsg = tid & 7;

        float4 abuf[4];
        auto ldg_A = [&](int kc) {
            const float* g = A + kc * 32 + afsg * 4;
            #pragma unroll
            for (int t = 0; t < 4; t++)
                abuf[t] = *reinterpret_cast<const float4*>(g + (size_t)arow[t] * DD);
        };
        auto sts_A = [&](int st) {
            char* base = smem + st * STAGE_B;
            #pragma unroll
            for (int t = 0; t < 4; t++) {
                uint2 h;
                h.x = pack_h2(abuf[t].x, abuf[t].y);
                h.y = pack_h2(abuf[t].z, abuf[t].w);
                *reinterpret_cast<uint2*>(base + arow[t] * PH + afsg * 8) = h;
            }
        };
        auto cp_B = [&](int kc, int st) {
            #pragma unroll
            for (int t = 0; t < 2; t++) {
                int iid = tid + t * 256;
                int row = iid >> 2, seg = iid & 3;
                cp_async16(sb + st * STAGE_B + TILE_B + row * PH + seg * 16,
                           B + (size_t)row * DD + kc * 32 + seg * 8);
            }
            cp_commit();
        };

        float acc[2][8][4];
        #pragma unroll
        for (int i = 0; i < 2; i++)
            #pragma unroll
            for (int j = 0; j < 8; j++)
                #pragma unroll
                for (int k = 0; k < 4; k++) acc[i][j][k] = 0.f;

        ldg_A(0);
        cp_B(0, 0);

        const int lrow = lane & 15;
        const int lhalf = lane >> 4;

        #pragma unroll 1
        for (int c = 0; c < NCHUNK; c++) {
            const int s = c & 1;
            sts_A(s);
            if (c + 1 < NCHUNK) {
                ldg_A(c + 1);
                cp_B(c + 1, s ^ 1);
                cp_wait<1>();
            } else {
                cp_wait<0>();
            }
            __syncthreads();

            const uint32_t stg = sb + s * STAGE_B;
            #pragma unroll
            for (int ks = 0; ks < 2; ks++) {
                const int seg = ks * 2 + lhalf;
                uint32_t ah[2][4];
                #pragma unroll
                for (int mf = 0; mf < 2; mf++) {
                    uint32_t off = (uint32_t)((wm * 32 + mf * 16 + lrow) * PH + seg * 16);
                    ldmatrix_x4(ah[mf][0], ah[mf][1], ah[mf][2], ah[mf][3], stg + off);
                }
                #pragma unroll
                for (int ng = 0; ng < 4; ng++) {
                    uint32_t off = (uint32_t)((wn * 64 + ng * 16 + lrow) * PH + seg * 16);
                    uint32_t b0, b1, b2, b3;
                    ldmatrix_x4(b0, b1, b2, b3, stg + TILE_B + off);
                    #pragma unroll
                    for (int mf = 0; mf < 2; mf++) {
                        mma_f16(acc[mf][2*ng  ], ah[mf], b0, b2);
                        mma_f16(acc[mf][2*ng+1], ah[mf], b1, b3);
                    }
                }
            }
            __syncthreads();
        }

        #pragma unroll
        for (int nf = 0; nf < 8; nf++) {
            const int col = n0 + wn * 64 + nf * 8 + (lane & 3) * 2;
            const float b0 = bias[col], b1 = bias[col + 1];
            #pragma unroll
            for (int mf = 0; mf < 2; mf++) {
                const int r0 = m0 + wm * 32 + mf * 16 + (lane >> 2);
                const float* a = acc[mf][nf];
                #pragma unroll
                for (int half = 0; half < 2; half++) {
                    const int m = r0 + half * 8;
                    uint32_t hp = pack_h2((a[2*half] + b0) * scale,
                                          (a[2*half+1] + b1) * scale);
                    int bb = m >> 10, l = m & 1023;
                    int hh = col >> 6, d = col & 63;
                    size_t idx = (((size_t)(bb * HH + hh) << 10) + l) * DHH + d;
                    *reinterpret_cast<uint32_t*>(oh + idx) = hp;
                }
            }
        }

        __syncthreads();
        if (tid == 0) {
            __threadfence();
            atomicAdd(&g_qkv[(b * 6 + nt) * 3 + z], 1);
        }

    } else if (blockIdx.x < 1920) {
        // =================== ATTENTION ROLE ===================
        const int id = blockIdx.x - 1152;
        const int qt = id & 7, h = (id >> 3) % 12, b = id / 96;
        const int q0 = qt * 128;
        const size_t hb = ((size_t)(b * HH + h)) << 16;

        if (tid == 0) {
            const int base = (b * 6 + (h >> 1)) * 3;
            while (atomicAdd(&g_qkv[base + 0], 0) < 8 ||
                   atomicAdd(&g_qkv[base + 1], 0) < 8 ||
                   atomicAdd(&g_qkv[base + 2], 0) < 8) __nanosleep(128);
            __threadfence();
        }
        __syncthreads();

        const uint32_t SQ = sb;
        auto stage = [&](int s) { return sb + QTILE_B + (uint32_t)s * 2 * KTILE_B; };

        auto load_q = [&]() {
            const __half* g = g_q16 + hb + (size_t)q0 * 64;
            #pragma unroll
            for (int it = 0; it < 4; it++) {
                int iid = tid + it * 256;
                int row = iid >> 3, seg = iid & 7;
                cp_async16(SQ + row * AROWB + seg * 16, g + (size_t)row * 64 + seg * 8);
            }
            cp_commit();
        };
        auto load_kv = [&](int t, int s) {
            const size_t off = hb + (size_t)t * 64 * 64;
            uint32_t st = stage(s);
            #pragma unroll
            for (int it = 0; it < 2; it++) {
                int iid = tid + it * 256;
                int row = iid >> 3, seg = iid & 7;
                cp_async16(st + row * AROWB + seg * 16,
                           g_k16 + off + (size_t)row * 64 + seg * 8);
                cp_async16(st + KTILE_B + row * AROWB + seg * 16,
                           g_v16 + off + (size_t)row * 64 + seg * 8);
            }
            cp_commit();
        };

        load_q();
        load_kv(0, 0);
        cp_wait<1>();
        __syncthreads();

        const int lr = lane & 15, lh = lane >> 4;
        uint32_t qf[4][4];
        #pragma unroll
        for (int ks = 0; ks < 4; ks++) {
            uint32_t off = (uint32_t)((wid * 16 + lr) * AROWB + ks * 32 + lh * 16);
            ldmatrix_x4(qf[ks][0], qf[ks][1], qf[ks][2], qf[ks][3], SQ + off);
        }

        float mA = -INFINITY, mB = -INFINITY, lA = 0.f, lB = 0.f;
        float o[8][4];
        #pragma unroll
        for (int i = 0; i < 8; i++)
            #pragma unroll
            for (int j = 0; j < 4; j++) o[i][j] = 0.f;

        const unsigned char* flagp = g_mflags + (b * 8 + qt) * 8;
        const uint32_t ONES2 = 0x3C003C00u;   // half2(1.0, 1.0)

        #pragma unroll 1
        for (int t = 0; t < 16; t++) {
            if (t < 15) { load_kv(t + 1, (t + 1) & 1); cp_wait<1>(); }
            else        { cp_wait<0>(); }
            __syncthreads();
            const uint32_t st = stage(t & 1);

            float s[8][4];
            #pragma unroll
            for (int j = 0; j < 8; j++)
                #pragma unroll
                for (int k = 0; k < 4; k++) s[j][k] = 0.f;

            #pragma unroll
            for (int ks = 0; ks < 4; ks++) {
                #pragma unroll
                for (int ng = 0; ng < 4; ng++) {
                    uint32_t off = (uint32_t)((ng * 16 + lr) * AROWB + ks * 32 + lh * 16);
                    uint32_t k0, k1, k2, k3;
                    ldmatrix_x4(k0, k1, k2, k3, st + off);
                    mma_f16(s[2*ng  ], qf[ks], k0, k2);
                    mma_f16(s[2*ng+1], qf[ks], k1, k3);
                }
            }

            if (flagp[t >> 1]) {
                const uint32_t* mr = g_mbits
                    + ((size_t)(b * LL + q0 + wid * 16 + (lane >> 2))) * (LL / 32) + t * 2;
                uint32_t wA[2], wB[2];
                #pragma unroll
                for (int ww = 0; ww < 2; ww++) { wA[ww] = mr[ww]; wB[ww] = mr[8 * (LL/32) + ww]; }
                #pragma unroll
                for (int j = 0; j < 8; j++) {
                    int bp = (j & 3) * 8 + (lane & 3) * 2;
                    uint32_t a = wA[j >> 2], bw = wB[j >> 2];
                    if ((a  >> bp)      & 1u) s[j][0] = -INFINITY;
                    if ((a  >> (bp+1))  & 1u) s[j][1] = -INFINITY;
                    if ((bw >> bp)      & 1u) s[j][2] = -INFINITY;
                    if ((bw >> (bp+1))  & 1u) s[j][3] = -INFINITY;
                }
            }

            float mxA = -INFINITY, mxB = -INFINITY;
            #pragma unroll
            for (int j = 0; j < 8; j++) {
                mxA = fmaxf(mxA, fmaxf(s[j][0], s[j][1]));
                mxB = fmaxf(mxB, fmaxf(s[j][2], s[j][3]));
            }
            mxA = fmaxf(mxA, __shfl_xor_sync(0xffffffffu, mxA, 1));
            mxA = fmaxf(mxA, __shfl_xor_sync(0xffffffffu, mxA, 2));
            mxB = fmaxf(mxB, __shfl_xor_sync(0xffffffffu, mxB, 1));
            mxB = fmaxf(mxB, __shfl_xor_sync(0xffffffffu, mxB, 2));
            float mnA = fmaxf(mA, mxA), mnB = fmaxf(mB, mxB);
            float aA = (mA == -INFINITY) ? 0.f : exp2f(mA - mnA);
            float aB = (mB == -INFINITY) ? 0.f : exp2f(mB - mnB);
            float subA = (mnA == -INFINITY) ? 0.f : mnA;
            float subB = (mnB == -INFINITY) ? 0.f : mnB;
            mA = mnA; mB = mnB;
            if (aA != 1.f || aB != 1.f) {
                #pragma unroll
                for (int nf = 0; nf < 8; nf++) {
                    o[nf][0] *= aA; o[nf][1] *= aA;
                    o[nf][2] *= aB; o[nf][3] *= aB;
                }
            }

            float sf[4] = {0.f, 0.f, 0.f, 0.f};
            #pragma unroll
            for (int ks = 0; ks < 4; ks++) {
                uint32_t ap[4];
                ap[0] = ex2_h2(pack_h2(s[2*ks  ][0] - subA, s[2*ks  ][1] - subA));
                ap[1] = ex2_h2(pack_h2(s[2*ks  ][2] - subB, s[2*ks  ][3] - subB));
                ap[2] = ex2_h2(pack_h2(s[2*ks+1][0] - subA, s[2*ks+1][1] - subA));
                ap[3] = ex2_h2(pack_h2(s[2*ks+1][2] - subB, s[2*ks+1][3] - subB));
                mma_f16(sf, ap, ONES2, ONES2);   // col = row sum of P
                #pragma unroll
                for (int ng = 0; ng < 4; ng++) {
                    uint32_t voff = (uint32_t)((ks * 16 + lr) * AROWB + ng * 32 + lh * 16);
                    uint32_t v0, v1, v2, v3;
                    ldmatrix_x4_t(v0, v1, v2, v3, st + KTILE_B + voff);
                    mma_f16(o[2*ng  ], ap, v0, v1);
                    mma_f16(o[2*ng+1], ap, v2, v3);
                }
            }
            lA = lA * aA + sf[0];
            lB = lB * aB + sf[2];
            __syncthreads();
        }

        float iA = (lA > 0.f) ? (1.f / lA) : 0.f;
        float iB = (lB > 0.f) ? (1.f / lB) : 0.f;
        size_t rowA = (size_t)b * LL + q0 + wid * 16 + (lane >> 2);
        size_t rowB = rowA + 8;
        #pragma unroll
        for (int nf = 0; nf < 8; nf++) {
            int col = h * 64 + nf * 8 + (lane & 3) * 2;
            *reinterpret_cast<uint32_t*>(g_c16 + rowA * DD + col)
                = pack_h2(o[nf][0] * iA, o[nf][1] * iA);
            *reinterpret_cast<uint32_t*>(g_c16 + rowB * DD + col)
                = pack_h2(o[nf][2] * iB, o[nf][3] * iB);
        }

        __syncthreads();
        if (tid == 0) {
            __threadfence();
            atomicAdd(&g_sync[b * 8 + qt], 1);
        }
    } else {
        // =================== OUT-PROJECTION ROLE ===================
        const int oid = blockIdx.x - 1920;     // 768 tiles: 128 m x 6 n
        const int mt = oid & 127;
        const int nt = oid >> 7;
        const int wm = wid & 3, wn = wid >> 2;

        const int flag = (mt >> 4) * 8 + ((mt & 15) >> 1);
        if (tid == 0) {
            while (atomicAdd(&g_sync[flag], 0) < HH) __nanosleep(128);
            __threadfence();
        }
        __syncthreads();

        const __half* A = g_c16 + (size_t)mt * 64 * DD;
        const __half* B = g_w16[3] + (size_t)nt * 128 * DD;

        auto load_chunk = [&](int kc, int st) {
            #pragma unroll
            for (int t = 0; t < 3; t++) {
                int iid = tid + t * 256;            // 0..767
                uint32_t dst; const __half* src;
                if (iid < 256) {
                    int row = iid >> 2, seg = iid & 3;
                    dst = sb + st * OSTAGE + row * PH + seg * 16;
                    src = A + (size_t)row * DD + kc * 32 + seg * 8;
                } else {
                    int rem = iid - 256;
                    int row = rem >> 2, seg = rem & 3;
                    dst = sb + st * OSTAGE + OA_TILE + row * PH + seg * 16;
                    src = B + (size_t)row * DD + kc * 32 + seg * 8;
                }
                cp_async16(dst, src);
            }
            cp_commit();
        };

        float acc[8][4];
        #pragma unroll
        for (int j = 0; j < 8; j++)
            #pragma unroll
            for (int k = 0; k < 4; k++) acc[j][k] = 0.f;

        load_chunk(0, 0);

        const int lrow = lane & 15;
        const int lhalf = lane >> 4;

        #pragma unroll 1
        for (int c = 0; c < NCHUNK; c++) {
            const int s = c & 1;
            if (c + 1 < NCHUNK) { load_chunk(c + 1, s ^ 1); cp_wait<1>(); }
            else                { cp_wait<0>(); }
            __syncthreads();

            const uint32_t stg = sb + s * OSTAGE;
            #pragma unroll
            for (int ks = 0; ks < 2; ks++) {
                const int seg = ks * 2 + lhalf;
                uint32_t ah[4];
                uint32_t aoff = (uint32_t)((wm * 16 + lrow) * PH + seg * 16);
                ldmatrix_x4(ah[0], ah[1], ah[2], ah[3], stg + aoff);
                #pragma unroll
                for (int ng = 0; ng < 4; ng++) {
                    uint32_t boff = (uint32_t)((wn * 64 + ng * 16 + lrow) * PH + seg * 16);
                    uint32_t b0, b1, b2, b3;
                    ldmatrix_x4(b0, b1, b2, b3, stg + OA_TILE + boff);
                    mma_f16(acc[2*ng  ], ah, b0, b2);
                    mma_f16(acc[2*ng+1], ah, b1, b3);
                }
            }
            __syncthreads();
        }

        #pragma unroll
        for (int nf = 0; nf < 8; nf++) {
            const int col = nt * 128 + wn * 64 + nf * 8 + (lane & 3) * 2;
            const float b0 = bias_o[col], b1 = bias_o[col + 1];
            const int r0 = mt * 64 + wm * 16 + (lane >> 2);
            #pragma unroll
            for (int half = 0; half < 2; half++) {
                const int m = r0 + half * 8;
                *reinterpret_cast<float2*>(out + (size_t)m * DD + col)
                    = make_float2(acc[nf][2*half] + b0, acc[nf][2*half+1] + b1);
            }
        }
    }
}

// ---------------------------------------------------------------------------
extern "C" void kernel_launch(void* const* d_in, const int* in_sizes, int n_in,
                              void* d_out, int out_size)
{
    const float* Query = (const float*)d_in[0];
    const float* Key   = (const float*)d_in[1];
    const float* Value = (const float*)d_in[2];
    const unsigned char* maskp = (const unsigned char*)d_in[3];
    const float* WQ_b = (const float*)d_in[5];
    const float* WK_b = (const float*)d_in[7];
    const float* WV_b = (const float*)d_in[9];
    const float* WO_b = (const float*)d_in[11];
    float* out = (float*)d_out;

    cudaFuncSetAttribute(mha_mega, cudaFuncAttributeMaxDynamicSharedMemorySize,
                         ASMEM);

    // Prep: mask pack/flags + counter reset + weight converts (one launch)
    prep_all<<<1088, 256>>>(maskp,
                            (const float*)d_in[4], (const float*)d_in[6],
                            (const float*)d_in[8], (const float*)d_in[10]);

    // Everything else: one launch
    mha_mega<<<2688, 256, ASMEM>>>(Query, Key, Value,
                                   WQ_b, WK_b, WV_b, WO_b, out);
}